// round 16
// baseline (speedup 1.0000x reference)
#include <cuda_runtime.h>
#include <math.h>

// Fixed dataset sizes: N=50000 nodes, E=800000 edges, +N self-loops.
#define NMAX 50000
#define EMAX 800000
#define ETMAX (NMAX + EMAX)

// ---------------- static device scratch (no allocations allowed) ---------------
__device__ float  g_bufA[(size_t)NMAX * 256];   // h = in @ W
__device__ float  g_bufB[(size_t)NMAX * 256];   // aggregated output / next input
__device__ float  g_s[NMAX * 4];
__device__ float  g_d[NMAX * 4];
__device__ float  g_m[NMAX * 4];
__device__ float  g_den[NMAX * 4];
__device__ int    g_src[ETMAX];
__device__ int    g_dst[ETMAX];
__device__ int    g_deg[NMAX];
__device__ int    g_rowstart[NMAX + 1];
__device__ int    g_cursor[NMAX];
__device__ int    g_csr_src[ETMAX];
__device__ int    g_is64;
__device__ double g_sum[256];
__device__ double g_sq[256];
__device__ float  g_scale[256];
__device__ float  g_shift[256];
__device__ double g_psum[64];
__device__ float  g_pmax[64];

// Ordered-int float max; safe for mixed signs when initialized to -inf.
__device__ __forceinline__ void atomicMaxF(float* addr, float v) {
    if (v >= 0.f) atomicMax((int*)addr, __float_as_int(v));
    else          atomicMin((unsigned int*)addr, __float_as_uint(v));
}

// ---------------- edge-index dtype probe + int32 materialization ---------------
__global__ void k_detect(const int* __restrict__ words) {
    if (threadIdx.x == 0) {
        int wide = 1;
        for (int q = 0; q < 128; q++)
            if (words[2 * q + 1] != 0) { wide = 0; break; }
        g_is64 = wide;
    }
}

__global__ void k_cvt(const int* __restrict__ words, int E, int ET) {
    int i = blockIdx.x * blockDim.x + threadIdx.x;
    if (i >= ET) return;
    int sv, dv;
    if (i < E) {
        if (g_is64) { sv = words[2 * (size_t)i]; dv = words[2 * ((size_t)E + i)]; }
        else        { sv = words[i];             dv = words[E + i]; }
    } else {
        sv = dv = i - E;   // appended self-loops
    }
    g_src[i] = sv;
    g_dst[i] = dv;
}

// ---------------- CSR-by-dst build: histogram, scan, scatter -------------------
__global__ void k_hist(int ET) {
    int i = blockIdx.x * blockDim.x + threadIdx.x;
    if (i < ET) atomicAdd(&g_deg[g_dst[i]], 1);
}

// One-block scan: per-thread chunk sums -> two-level shuffle scan -> writeback.
__global__ void k_scan(int Nn) {
    __shared__ int wsum[32];
    const int t = threadIdx.x;                  // 0..1023
    const int chunk = (Nn + 1023) / 1024;
    const int lo = t * chunk;
    const int hi = min(lo + chunk, Nn);
    const int lane = t & 31, wrp = t >> 5;

    int local = 0;
    for (int i = lo; i < hi; i++) local += g_deg[i];

    int incl = local;
#pragma unroll
    for (int o = 1; o < 32; o <<= 1) {
        int u = __shfl_up_sync(0xffffffffu, incl, o);
        if (lane >= o) incl += u;
    }
    if (lane == 31) wsum[wrp] = incl;
    __syncthreads();
    if (wrp == 0) {
        int wv = wsum[lane];
#pragma unroll
        for (int o = 1; o < 32; o <<= 1) {
            int u = __shfl_up_sync(0xffffffffu, wv, o);
            if (lane >= o) wv += u;
        }
        wsum[lane] = wv;
    }
    __syncthreads();
    int excl = incl - local + (wrp ? wsum[wrp - 1] : 0);

    int run = excl;
    for (int i = lo; i < hi; i++) {
        int dg = g_deg[i];
        g_rowstart[i] = run;
        g_cursor[i] = run;
        run += dg;
    }
    // Every thread whose (possibly empty) chunk ends at Nn writes the identical total.
    if (hi == Nn) g_rowstart[Nn] = run;
}

__global__ void k_scatter(int ET) {
    int i = blockIdx.x * blockDim.x + threadIdx.x;
    if (i >= ET) return;
    int slot = atomicAdd(&g_cursor[g_dst[i]], 1);
    g_csr_src[slot] = g_src[i];
}

// ---------------- SGEMM + fused attention-projection epilogue ------------------
// C[M,N] = BNReLU(A)[M,K] @ B[K,N]; row-major; K%16==0, N%TN==0.
// When aprj != nullptr: also emits s[r,h]=sum_c h[r,c]*asrc[c] and the same for
// adst, reduced from the accumulators (zero extra global traffic on h).
template<int TM, int TN>
__global__ void __launch_bounds__((TM/8)*(TN/8))
k_sgemm_opt(const float* __restrict__ A, const float* __restrict__ B,
            float* __restrict__ C, int M, int N, int K,
            const float* __restrict__ bnscale, const float* __restrict__ bnshift,
            const float* __restrict__ aprj, const float* __restrict__ dprj) {
    constexpr int BK = 16;
    constexpr int NT = (TM / 8) * (TN / 8);
    constexpr int AV = TM * BK / 4 / NT;
    constexpr int BV = BK * TN / 4 / NT;
    constexpr int TG = TN / 8;                  // lanes per row group (16 or 8)
    __shared__ float As[2][BK][TM + 4];
    __shared__ float Bs[2][BK][TN];

    const int tid = threadIdx.x;
    const int tx = tid % TG;
    const int ty = tid / TG;
    const int rb = blockIdx.y * TM;
    const int cb = blockIdx.x * TN;

    float4 aF[AV], bF[BV];
    float acc[8][8];
#pragma unroll
    for (int i = 0; i < 8; i++)
#pragma unroll
        for (int j = 0; j < 8; j++) acc[i][j] = 0.f;

    // prologue: slab 0 -> registers
#pragma unroll
    for (int i = 0; i < AV; i++) {
        const int idx = tid + i * NT;
        const int r = idx / (BK / 4);
        const int c = (idx % (BK / 4)) * 4;
        float4 v = make_float4(0.f, 0.f, 0.f, 0.f);
        if (rb + r < M) v = *(const float4*)(A + (size_t)(rb + r) * K + c);
        if (bnscale) {
            float4 sc = *(const float4*)(bnscale + c);
            float4 sh = *(const float4*)(bnshift + c);
            v.x = fmaxf(fmaf(v.x, sc.x, sh.x), 0.f);
            v.y = fmaxf(fmaf(v.y, sc.y, sh.y), 0.f);
            v.z = fmaxf(fmaf(v.z, sc.z, sh.z), 0.f);
            v.w = fmaxf(fmaf(v.w, sc.w, sh.w), 0.f);
        }
        aF[i] = v;
    }
#pragma unroll
    for (int i = 0; i < BV; i++) {
        const int idx = tid + i * NT;
        const int r = idx / (TN / 4);
        const int c = (idx % (TN / 4)) * 4;
        bF[i] = *(const float4*)(B + (size_t)r * N + cb + c);
    }
#pragma unroll
    for (int i = 0; i < AV; i++) {
        const int idx = tid + i * NT;
        const int r = idx / (BK / 4);
        const int c = (idx % (BK / 4)) * 4;
        As[0][c + 0][r] = aF[i].x;
        As[0][c + 1][r] = aF[i].y;
        As[0][c + 2][r] = aF[i].z;
        As[0][c + 3][r] = aF[i].w;
    }
#pragma unroll
    for (int i = 0; i < BV; i++) {
        const int idx = tid + i * NT;
        const int r = idx / (TN / 4);
        const int c = (idx % (TN / 4)) * 4;
        *(float4*)&Bs[0][r][c] = bF[i];
    }
    __syncthreads();

    int buf = 0;
    for (int k0 = BK; k0 < K; k0 += BK) {
#pragma unroll
        for (int i = 0; i < AV; i++) {
            const int idx = tid + i * NT;
            const int r = idx / (BK / 4);
            const int c = (idx % (BK / 4)) * 4;
            float4 v = make_float4(0.f, 0.f, 0.f, 0.f);
            if (rb + r < M) v = *(const float4*)(A + (size_t)(rb + r) * K + k0 + c);
            if (bnscale) {
                float4 sc = *(const float4*)(bnscale + k0 + c);
                float4 sh = *(const float4*)(bnshift + k0 + c);
                v.x = fmaxf(fmaf(v.x, sc.x, sh.x), 0.f);
                v.y = fmaxf(fmaf(v.y, sc.y, sh.y), 0.f);
                v.z = fmaxf(fmaf(v.z, sc.z, sh.z), 0.f);
                v.w = fmaxf(fmaf(v.w, sc.w, sh.w), 0.f);
            }
            aF[i] = v;
        }
#pragma unroll
        for (int i = 0; i < BV; i++) {
            const int idx = tid + i * NT;
            const int r = idx / (TN / 4);
            const int c = (idx % (TN / 4)) * 4;
            bF[i] = *(const float4*)(B + (size_t)(k0 + r) * N + cb + c);
        }
#pragma unroll
        for (int kk = 0; kk < BK; kk++) {
            float a[8], b[8];
            *(float4*)&a[0] = *(const float4*)&As[buf][kk][ty * 4];
            *(float4*)&a[4] = *(const float4*)&As[buf][kk][TM / 2 + ty * 4];
            *(float4*)&b[0] = *(const float4*)&Bs[buf][kk][tx * 4];
            *(float4*)&b[4] = *(const float4*)&Bs[buf][kk][TN / 2 + tx * 4];
#pragma unroll
            for (int i = 0; i < 8; i++)
#pragma unroll
                for (int j = 0; j < 8; j++)
                    acc[i][j] = fmaf(a[i], b[j], acc[i][j]);
        }
#pragma unroll
        for (int i = 0; i < AV; i++) {
            const int idx = tid + i * NT;
            const int r = idx / (BK / 4);
            const int c = (idx % (BK / 4)) * 4;
            As[buf ^ 1][c + 0][r] = aF[i].x;
            As[buf ^ 1][c + 1][r] = aF[i].y;
            As[buf ^ 1][c + 2][r] = aF[i].z;
            As[buf ^ 1][c + 3][r] = aF[i].w;
        }
#pragma unroll
        for (int i = 0; i < BV; i++) {
            const int idx = tid + i * NT;
            const int r = idx / (TN / 4);
            const int c = (idx % (TN / 4)) * 4;
            *(float4*)&Bs[buf ^ 1][r][c] = bF[i];
        }
        __syncthreads();
        buf ^= 1;
    }
#pragma unroll
    for (int kk = 0; kk < BK; kk++) {
        float a[8], b[8];
        *(float4*)&a[0] = *(const float4*)&As[buf][kk][ty * 4];
        *(float4*)&a[4] = *(const float4*)&As[buf][kk][TM / 2 + ty * 4];
        *(float4*)&b[0] = *(const float4*)&Bs[buf][kk][tx * 4];
        *(float4*)&b[4] = *(const float4*)&Bs[buf][kk][TN / 2 + tx * 4];
#pragma unroll
        for (int i = 0; i < 8; i++)
#pragma unroll
            for (int j = 0; j < 8; j++)
                acc[i][j] = fmaf(a[i], b[j], acc[i][j]);
    }

    // store C
#pragma unroll
    for (int i = 0; i < 8; i++) {
        int r = rb + (i < 4 ? ty * 4 + i : TM / 2 + ty * 4 + (i - 4));
        if (r < M) {
            float4 v0 = make_float4(acc[i][0], acc[i][1], acc[i][2], acc[i][3]);
            float4 v1 = make_float4(acc[i][4], acc[i][5], acc[i][6], acc[i][7]);
            *(float4*)(C + (size_t)r * N + cb + tx * 4) = v0;
            *(float4*)(C + (size_t)r * N + cb + TN / 2 + tx * 4) = v1;
        }
    }

    // fused s/d projections from live accumulators
    if (aprj) {
        float pa0[4], pa1[4], pd0[4], pd1[4];
#pragma unroll
        for (int j = 0; j < 4; j++) {
            pa0[j] = aprj[cb + tx * 4 + j];
            pa1[j] = aprj[cb + TN / 2 + tx * 4 + j];
            pd0[j] = dprj[cb + tx * 4 + j];
            pd1[j] = dprj[cb + TN / 2 + tx * 4 + j];
        }
        const int headLo = cb >> 6;   // TN==128: this block covers heads {headLo, headLo+1}
#pragma unroll
        for (int i = 0; i < 8; i++) {
            float sA = 0.f, dA = 0.f, sB = 0.f, dB = 0.f;
#pragma unroll
            for (int j = 0; j < 4; j++) {
                sA = fmaf(acc[i][j], pa0[j], sA);
                dA = fmaf(acc[i][j], pd0[j], dA);
                sB = fmaf(acc[i][4 + j], pa1[j], sB);
                dB = fmaf(acc[i][4 + j], pd1[j], dB);
            }
#pragma unroll
            for (int o = TG / 2; o >= 1; o >>= 1) {
                sA += __shfl_xor_sync(0xffffffffu, sA, o);
                dA += __shfl_xor_sync(0xffffffffu, dA, o);
                sB += __shfl_xor_sync(0xffffffffu, sB, o);
                dB += __shfl_xor_sync(0xffffffffu, dB, o);
            }
            if (tx == 0) {
                int r = rb + (i < 4 ? ty * 4 + i : TM / 2 + ty * 4 + (i - 4));
                if (r < M) {
                    if (TN == 128) {          // two heads (H=4 layout)
                        g_s[r * 4 + headLo]     = sA;
                        g_s[r * 4 + headLo + 1] = sB;
                        g_d[r * 4 + headLo]     = dA;
                        g_d[r * 4 + headLo + 1] = dB;
                    } else {                  // single head (H=1 layout)
                        g_s[r] = sA + sB;
                        g_d[r] = dA + dB;
                    }
                }
            }
        }
    }
}

// ---------------- online-softmax primitives ------------------------------------
__device__ __forceinline__ void osm_upd(float& m, float& s, float e) {
    float mn = fmaxf(m, e);
    s = s * expf(m - mn) + expf(e - mn);
    m = mn;
}
__device__ __forceinline__ void osm_merge(float& m, float& s, float mo, float so) {
    float mn = fmaxf(m, mo);
    s = s * expf(m - mn) + so * expf(mo - mn);
    m = mn;
}

// ---------------- CSR segment softmax: one warp per destination ----------------
__global__ void k_smax4(int Nn) {
    int w = (int)((blockIdx.x * (size_t)blockDim.x + threadIdx.x) >> 5);
    int lane = threadIdx.x & 31;
    if (w >= Nn) return;
    int rs = g_rowstart[w], re = g_rowstart[w + 1];
    float4 d4 = *(const float4*)&g_d[w * 4];
    float4 m = make_float4(-3.0e38f, -3.0e38f, -3.0e38f, -3.0e38f);
    float4 s = make_float4(0.f, 0.f, 0.f, 0.f);
    for (int p = rs + lane; p < re; p += 32) {
        int src = g_csr_src[p];
        float4 sv = *(const float4*)&g_s[src * 4];
        float4 e;
        e.x = sv.x + d4.x; e.x = e.x > 0.f ? e.x : 0.2f * e.x;
        e.y = sv.y + d4.y; e.y = e.y > 0.f ? e.y : 0.2f * e.y;
        e.z = sv.z + d4.z; e.z = e.z > 0.f ? e.z : 0.2f * e.z;
        e.w = sv.w + d4.w; e.w = e.w > 0.f ? e.w : 0.2f * e.w;
        osm_upd(m.x, s.x, e.x);
        osm_upd(m.y, s.y, e.y);
        osm_upd(m.z, s.z, e.z);
        osm_upd(m.w, s.w, e.w);
    }
#pragma unroll
    for (int o = 16; o; o >>= 1) {
        float mo, so;
        mo = __shfl_xor_sync(0xffffffffu, m.x, o); so = __shfl_xor_sync(0xffffffffu, s.x, o);
        osm_merge(m.x, s.x, mo, so);
        mo = __shfl_xor_sync(0xffffffffu, m.y, o); so = __shfl_xor_sync(0xffffffffu, s.y, o);
        osm_merge(m.y, s.y, mo, so);
        mo = __shfl_xor_sync(0xffffffffu, m.z, o); so = __shfl_xor_sync(0xffffffffu, s.z, o);
        osm_merge(m.z, s.z, mo, so);
        mo = __shfl_xor_sync(0xffffffffu, m.w, o); so = __shfl_xor_sync(0xffffffffu, s.w, o);
        osm_merge(m.w, s.w, mo, so);
    }
    if (lane == 0) {
        *(float4*)&g_m[w * 4] = m;
        *(float4*)&g_den[w * 4] = s;
    }
}

__global__ void k_smax1(int Nn) {
    int w = (int)((blockIdx.x * (size_t)blockDim.x + threadIdx.x) >> 5);
    int lane = threadIdx.x & 31;
    if (w >= Nn) return;
    int rs = g_rowstart[w], re = g_rowstart[w + 1];
    float dv = g_d[w];
    float m = -3.0e38f, s = 0.f;
    for (int p = rs + lane; p < re; p += 32) {
        int src = g_csr_src[p];
        float e = g_s[src] + dv;
        e = e > 0.f ? e : 0.2f * e;
        osm_upd(m, s, e);
    }
#pragma unroll
    for (int o = 16; o; o >>= 1) {
        float mo = __shfl_xor_sync(0xffffffffu, m, o);
        float so = __shfl_xor_sync(0xffffffffu, s, o);
        osm_merge(m, s, mo, so);
    }
    if (lane == 0) { g_m[w] = m; g_den[w] = s; }
}

// ---------------- CSR gather-aggregate: one warp per destination ---------------
__global__ void k_aggr_csr256(int Nn) {
    int w = (int)((blockIdx.x * (size_t)blockDim.x + threadIdx.x) >> 5);
    int lane = threadIdx.x & 31;
    if (w >= Nn) return;
    int rs = g_rowstart[w], re = g_rowstart[w + 1];
    float4 d4 = *(const float4*)&g_d[w * 4];
    float4 m4 = *(const float4*)&g_m[w * 4];
    float4 dn = *(const float4*)&g_den[w * 4];
    float4 ri;
    ri.x = 1.f / (dn.x + 1e-16f);
    ri.y = 1.f / (dn.y + 1e-16f);
    ri.z = 1.f / (dn.z + 1e-16f);
    ri.w = 1.f / (dn.w + 1e-16f);
    float4 acc0 = make_float4(0.f, 0.f, 0.f, 0.f);
    float4 acc1 = make_float4(0.f, 0.f, 0.f, 0.f);
    bool upper = (lane >= 16);
    int src = g_csr_src[rs];                   // >=1 edge per node (self-loop)
    for (int p = rs; p < re; p++) {
        int nxt = (p + 1 < re) ? g_csr_src[p + 1] : 0;    // hoist next index
        float4 sv = *(const float4*)&g_s[src * 4];        // warp-uniform load
        float4 e;
        e.x = sv.x + d4.x; e.x = e.x > 0.f ? e.x : 0.2f * e.x;
        e.y = sv.y + d4.y; e.y = e.y > 0.f ? e.y : 0.2f * e.y;
        e.z = sv.z + d4.z; e.z = e.z > 0.f ? e.z : 0.2f * e.z;
        e.w = sv.w + d4.w; e.w = e.w > 0.f ? e.w : 0.2f * e.w;
        float4 al;
        al.x = expf(e.x - m4.x) * ri.x;
        al.y = expf(e.y - m4.y) * ri.y;
        al.z = expf(e.z - m4.z) * ri.z;
        al.w = expf(e.w - m4.w) * ri.w;
        float a0 = upper ? al.y : al.x;   // head owning channels [4*lane ..]
        float a1 = upper ? al.w : al.z;   // head owning channels [128+4*lane ..]
        const float4* hp = (const float4*)(g_bufA + (size_t)src * 256);
        float4 v0 = hp[lane], v1 = hp[lane + 32];
        acc0.x = fmaf(a0, v0.x, acc0.x); acc0.y = fmaf(a0, v0.y, acc0.y);
        acc0.z = fmaf(a0, v0.z, acc0.z); acc0.w = fmaf(a0, v0.w, acc0.w);
        acc1.x = fmaf(a1, v1.x, acc1.x); acc1.y = fmaf(a1, v1.y, acc1.y);
        acc1.z = fmaf(a1, v1.z, acc1.z); acc1.w = fmaf(a1, v1.w, acc1.w);
        src = nxt;
    }
    float4* op = (float4*)(g_bufB + (size_t)w * 256);
    op[lane] = acc0;
    op[lane + 32] = acc1;
}

__global__ void k_aggr_csr64(int Nn) {
    int w = (int)((blockIdx.x * (size_t)blockDim.x + threadIdx.x) >> 5);
    int lane = threadIdx.x & 31;
    if (w >= Nn) return;
    int rs = g_rowstart[w], re = g_rowstart[w + 1];
    float dv = g_d[w];
    float m = g_m[w];
    float ri = 1.f / (g_den[w] + 1e-16f);
    float2 acc = make_float2(0.f, 0.f);
    int src = g_csr_src[rs];
    for (int p = rs; p < re; p++) {
        int nxt = (p + 1 < re) ? g_csr_src[p + 1] : 0;
        float e = g_s[src] + dv;
        e = e > 0.f ? e : 0.2f * e;
        float a = expf(e - m) * ri;
        float2 v = ((const float2*)(g_bufA + (size_t)src * 64))[lane];
        acc.x = fmaf(a, v.x, acc.x);
        acc.y = fmaf(a, v.y, acc.y);
        src = nxt;
    }
    ((float2*)(g_bufB + (size_t)w * 64))[lane] = acc;
}

// ---------------- batchnorm statistics (over x + bias) -------------------------
__global__ void k_bnstats(const float* __restrict__ X, const float* __restrict__ bias,
                          int Nn, int HC) {
    int tid = threadIdx.x;
    int ch = tid & (HC - 1);
    int rpb = blockDim.x / HC;
    int r = blockIdx.x * rpb + tid / HC;
    int stride = gridDim.x * rpb;
    float b = bias[ch];
    float s = 0.f, q = 0.f;
    for (; r < Nn; r += stride) {
        float xv = X[(size_t)r * HC + ch] + b;
        s += xv; q += xv * xv;
    }
    atomicAdd(&g_sum[ch], (double)s);
    atomicAdd(&g_sq[ch], (double)q);
}

__global__ void k_bnfin(const float* __restrict__ gamma, const float* __restrict__ beta,
                        const float* __restrict__ bias, int Nn, int HC) {
    int ch = threadIdx.x;
    if (ch >= HC) return;
    double mu = g_sum[ch] / Nn;
    double var = g_sq[ch] / Nn - mu * mu;
    float sc = (float)((double)gamma[ch] / sqrt(var + 1e-5));
    g_scale[ch] = sc;
    g_shift[ch] = beta[ch] + sc * (bias[ch] - (float)mu);
}

// ---------------- pooling with layer-2 BN+ReLU applied inline ------------------
__global__ void k_initpool() {
    int i = threadIdx.x;
    if (i < 64) { g_pmax[i] = -INFINITY; g_psum[i] = 0.0; }
}

__global__ void k_pool(const float* __restrict__ X, int Nn) {
    int tid = threadIdx.x;
    int ch = tid & 63;
    int rpb = blockDim.x >> 6;
    int r = blockIdx.x * rpb + (tid >> 6);
    int stride = gridDim.x * rpb;
    float sc = g_scale[ch], sh = g_shift[ch];
    float s = 0.f, mx = -INFINITY;
    for (; r < Nn; r += stride) {
        float xv = fmaxf(fmaf(X[(size_t)r * 64 + ch], sc, sh), 0.f);
        s += xv; mx = fmaxf(mx, xv);
    }
    atomicAdd(&g_psum[ch], (double)s);
    atomicMaxF(&g_pmax[ch], mx);
}

// ---------------- classifier head (single block) -------------------------------
__global__ void k_cls(const float* __restrict__ Wc1, const float* __restrict__ bc1,
                      const float* __restrict__ Wc2, const float* __restrict__ bc2,
                      int Nn, float* __restrict__ out) {
    __shared__ float pooled[128];
    __shared__ float z[64];
    int t = threadIdx.x;
    if (t < 64) pooled[t] = (float)(g_psum[t] / Nn);
    else        pooled[t] = g_pmax[t - 64];
    __syncthreads();
    if (t < 64) {
        float acc = bc1[t];
        for (int k = 0; k < 128; k++) acc += pooled[k] * Wc1[k * 64 + t];
        z[t] = fmaxf(acc, 0.f);
    }
    __syncthreads();
    if (t < 2) {
        float acc = bc2[t];
        for (int j = 0; j < 64; j++) acc += z[j] * Wc2[j * 2 + t];
        out[t] = acc;
    }
}

// ---------------- host-side driver ---------------------------------------------
extern "C" void kernel_launch(void* const* d_in, const int* in_sizes, int n_in,
                              void* d_out, int out_size) {
    const float* x   = (const float*)d_in[0];
    const int*   ei  = (const int*)d_in[1];   // int32 or LE-int64; probed on device
    const float* W0  = (const float*)d_in[2];  const float* b0  = (const float*)d_in[3];
    const float* as0 = (const float*)d_in[4];  const float* ad0 = (const float*)d_in[5];
    const float* gm0 = (const float*)d_in[6];  const float* bt0 = (const float*)d_in[7];
    const float* W1  = (const float*)d_in[8];  const float* b1  = (const float*)d_in[9];
    const float* as1 = (const float*)d_in[10]; const float* ad1 = (const float*)d_in[11];
    const float* gm1 = (const float*)d_in[12]; const float* bt1 = (const float*)d_in[13];
    const float* W2  = (const float*)d_in[14]; const float* b2  = (const float*)d_in[15];
    const float* as2 = (const float*)d_in[16]; const float* ad2 = (const float*)d_in[17];
    const float* gm2 = (const float*)d_in[18]; const float* bt2 = (const float*)d_in[19];
    const float* Wc1 = (const float*)d_in[20]; const float* bc1 = (const float*)d_in[21];
    const float* Wc2 = (const float*)d_in[22]; const float* bc2 = (const float*)d_in[23];

    const int Nn = in_sizes[0] / 128;
    const int E  = in_sizes[1] / 2;
    const int ET = E + Nn;

    float* bufA; float* bufB; float* scaleP; float* shiftP;
    void *sumP, *sqP, *psumP, *degP;
    cudaGetSymbolAddress((void**)&bufA, g_bufA);
    cudaGetSymbolAddress((void**)&bufB, g_bufB);
    cudaGetSymbolAddress((void**)&scaleP, g_scale);
    cudaGetSymbolAddress((void**)&shiftP, g_shift);
    cudaGetSymbolAddress(&sumP, g_sum);
    cudaGetSymbolAddress(&sqP, g_sq);
    cudaGetSymbolAddress(&psumP, g_psum);
    cudaGetSymbolAddress(&degP, g_deg);

    // dtype probe, src/dst materialization (+self-loops), CSR-by-dst build
    k_detect<<<1, 32>>>(ei);
    k_cvt<<<(ET + 255) / 256, 256>>>(ei, E, ET);
    cudaMemsetAsync(degP, 0, Nn * sizeof(int), 0);
    k_hist<<<(ET + 255) / 256, 256>>>(ET);
    k_scan<<<1, 1024>>>(Nn);
    k_scatter<<<(ET + 255) / 256, 256>>>(ET);

    const unsigned nwb = (unsigned)(((long long)Nn * 32 + 255) / 256);  // warp/node

    auto run_layer = [&](const float* in, int K, const float* W, const float* bias,
                         const float* asrc, const float* adst,
                         const float* gamma, const float* beta, int H, bool bnA) {
        const int HC = H * 64;
        const float* sc = bnA ? scaleP : nullptr;
        const float* sh = bnA ? shiftP : nullptr;
        if (HC == 256)
            k_sgemm_opt<128, 128><<<dim3(2, (Nn + 127) / 128), 256>>>(in, W, bufA, Nn, 256, K, sc, sh, asrc, adst);
        else
            k_sgemm_opt<128, 64><<<dim3(1, (Nn + 127) / 128), 128>>>(in, W, bufA, Nn, 64, K, sc, sh, asrc, adst);
        if (H == 4) {
            k_smax4<<<nwb, 256>>>(Nn);
            k_aggr_csr256<<<nwb, 256>>>(Nn);
        } else {
            k_smax1<<<nwb, 256>>>(Nn);
            k_aggr_csr64<<<nwb, 256>>>(Nn);
        }
        cudaMemsetAsync(sumP, 0, HC * sizeof(double), 0);
        cudaMemsetAsync(sqP, 0, HC * sizeof(double), 0);
        k_bnstats<<<512, 256>>>(bufB, bias, Nn, HC);
        k_bnfin<<<1, 256>>>(gamma, beta, bias, Nn, HC);
        // BN+ReLU is consumed downstream (next GEMM's A-load or k_pool).
    };

    run_layer(x,    128, W0, b0, as0, ad0, gm0, bt0, 4, false);
    run_layer(bufB, 256, W1, b1, as1, ad1, gm1, bt1, 4, true);
    run_layer(bufB, 256, W2, b2, as2, ad2, gm2, bt2, 1, true);

    cudaMemsetAsync(psumP, 0, 64 * sizeof(double), 0);
    k_initpool<<<1, 64>>>();
    k_pool<<<256, 256>>>(bufB, Nn);   // layer-2 BN+ReLU applied inline
    k_cls<<<1, 128>>>(Wc1, bc1, Wc2, bc2, Nn, (float*)d_out);
}